// round 5
// baseline (speedup 1.0000x reference)
#include <cuda_runtime.h>
#include <cstdint>

#define N_ 100000
#define E_ 3200000
#define NCAND 1024
#define CAP 4096
#define SCAN_B 256
#define NBLK ((N_ + SCAN_B - 1) / SCAN_B)   // 391

// ---------------- device scratch (static, no runtime allocation) ----------------
__device__ float2 g_fst [N_*32];
__device__ float2 g_emb1[N_*32];
__device__ uint2  g_edge[E_];          // CSR records: (col, val bits), segmented
__device__ unsigned char g_cls[E_];    // 0 = m12, 1 = m1-only, 2 = dropped
__device__ float  g_order0[N_];
__device__ float  g_order1[N_];
__device__ float  g_num1[N_];
__device__ unsigned g_cnt[N_];         // packed: deg | cnt_m1<<10 | cnt_m12<<20
__device__ unsigned g_cursor[N_];      // packed per-class cursors
__device__ unsigned g_seg[N_];         // cnt_m12 | cnt_m1<<16
__device__ int    g_rowptr[N_ + 1];
__device__ int    g_blocktot[NBLK];
__device__ int    g_blockoff[NBLK];
__device__ unsigned g_keys[N_];
__device__ unsigned g_hist[256];
__device__ unsigned g_prefix;
__device__ int g_rem;
__device__ int g_ticket;
__device__ int g_selcount;
__device__ unsigned long long g_cand[CAP];

// ---------------- Threefry-2x32 (20 rounds, 5 key injections) -------------------
#define TFR(a,b,r) { a += b; b = ((b << (r)) | (b >> (32-(r)))); b ^= a; }

__host__ __device__ __forceinline__ void tf2x32(unsigned k0, unsigned k1,
                                                unsigned& x0, unsigned& x1) {
    unsigned k2 = k0 ^ k1 ^ 0x1BD11BDAu;
    x0 += k0; x1 += k1;
    TFR(x0,x1,13) TFR(x0,x1,15) TFR(x0,x1,26) TFR(x0,x1,6)
    x0 += k1; x1 += k2 + 1u;
    TFR(x0,x1,17) TFR(x0,x1,29) TFR(x0,x1,16) TFR(x0,x1,24)
    x0 += k2; x1 += k0 + 2u;
    TFR(x0,x1,13) TFR(x0,x1,15) TFR(x0,x1,26) TFR(x0,x1,6)
    x0 += k0; x1 += k1 + 3u;
    TFR(x0,x1,17) TFR(x0,x1,29) TFR(x0,x1,16) TFR(x0,x1,24)
    x0 += k1; x1 += k2 + 4u;
    TFR(x0,x1,13) TFR(x0,x1,15) TFR(x0,x1,26) TFR(x0,x1,6)
    x0 += k2; x1 += k0 + 5u;
}

static void jax_split_part(unsigned k0, unsigned k1, unsigned* nk, unsigned* sk) {
    unsigned a0 = 0u, a1 = 0u; tf2x32(k0, k1, a0, a1);
    unsigned b0 = 0u, b1 = 1u; tf2x32(k0, k1, b0, b1);
    nk[0] = a0; nk[1] = a1;
    sk[0] = b0; sk[1] = b1;
}

__device__ __forceinline__ unsigned rb32(unsigned k0, unsigned k1, unsigned i) {
    unsigned x0 = 0u, x1 = i;
    tf2x32(k0, k1, x0, x1);
    return x0 ^ x1;
}

// ---------------- kernels -------------------------------------------------------

__global__ void k_zero() {
    int i = blockIdx.x * blockDim.x + threadIdx.x;
    if (i < N_) { g_cnt[i] = 0u; g_cursor[i] = 0u; }
    if (i < 256) g_hist[i] = 0u;
    if (i == 0) {
        g_prefix = 0u; g_rem = NCAND; g_selcount = 0; g_ticket = 0;
        g_rowptr[N_] = E_;
    }
}

// RNG masks (stored!) + packed per-row class counts (single atomic per edge)
__global__ void k_count(const int* __restrict__ rows,
                        unsigned a0, unsigned a1, unsigned b0, unsigned b1) {
    int e = blockIdx.x * blockDim.x + threadIdx.x;
    if (e >= E_) return;
    unsigned u1 = rb32(a0, a1, (unsigned)e);
    unsigned u2 = rb32(b0, b1, (unsigned)e);
    unsigned m1  = (u1 >= 0x80000000u) ? 1u : 0u;           // keep prob 0.5
    unsigned m12 = (m1 && u2 >= 0xC0000000u) ? 1u : 0u;     // joint keep
    g_cls[e] = (unsigned char)(m12 ? 0 : (m1 ? 1 : 2));
    int r = __ldg(rows + e);
    atomicAdd(&g_cnt[r], 1u + (m1 << 10) + (m12 << 20));
}

// ---- prefix scan over degrees -> rowptr; also emit segment counts ----
__global__ void k_scanA() {
    __shared__ int s[SCAN_B];
    int i = blockIdx.x * SCAN_B + threadIdx.x;
    s[threadIdx.x] = (i < N_) ? (int)(g_cnt[i] & 1023u) : 0;
    __syncthreads();
    for (int off = SCAN_B / 2; off > 0; off >>= 1) {
        if (threadIdx.x < off) s[threadIdx.x] += s[threadIdx.x + off];
        __syncthreads();
    }
    if (threadIdx.x == 0) g_blocktot[blockIdx.x] = s[0];
}

__global__ void k_scanB() {
    __shared__ int s[512];
    int t = threadIdx.x;
    int v0 = (t < NBLK) ? g_blocktot[t] : 0;
    s[t] = v0;
    __syncthreads();
    for (int off = 1; off < 512; off <<= 1) {
        int v = s[t];
        if (t >= off) v += s[t - off];
        __syncthreads();
        s[t] = v;
        __syncthreads();
    }
    if (t < NBLK) g_blockoff[t] = s[t] - v0;   // exclusive
}

__global__ void k_scanC() {
    __shared__ int s[SCAN_B];
    int i = blockIdx.x * SCAN_B + threadIdx.x;
    unsigned pc = (i < N_) ? g_cnt[i] : 0u;
    int d = (int)(pc & 1023u);
    s[threadIdx.x] = d;
    __syncthreads();
    for (int off = 1; off < SCAN_B; off <<= 1) {
        int v = s[threadIdx.x];
        if (threadIdx.x >= off) v += s[threadIdx.x - off];
        __syncthreads();
        s[threadIdx.x] = v;
        __syncthreads();
    }
    if (i < N_) {
        g_rowptr[i] = g_blockoff[blockIdx.x] + s[threadIdx.x] - d;
        unsigned cnt1  = (pc >> 10) & 1023u;
        unsigned cnt12 = (pc >> 20) & 1023u;
        g_seg[i] = cnt12 | (cnt1 << 16);
    }
}

// scatter edges into segmented CSR slots: [m12][m1-only][dropped]
__global__ void k_fill(const int* __restrict__ rows, const int* __restrict__ cols,
                       const float* __restrict__ vals) {
    int e = blockIdx.x * blockDim.x + threadIdx.x;
    if (e >= E_) return;
    int cls = (int)g_cls[e];

    int r = __ldg(rows + e);
    unsigned old = atomicAdd(&g_cursor[r], 1u << (10 * cls));
    unsigned within = (old >> (10 * cls)) & ((cls == 2) ? 0xFFFu : 1023u);
    unsigned seg = __ldg(&g_seg[r]);
    unsigned segbase = (cls == 0) ? 0u : ((cls == 1) ? (seg & 0xFFFFu) : (seg >> 16));
    int pos = __ldg(&g_rowptr[r]) + (int)(segbase + within);
    g_edge[pos] = make_uint2((unsigned)__ldg(cols + e), __float_as_uint(__ldg(vals + e)));
}

// ---- gather SpMM passes: 1 warp per row, float2 per lane ----
// PASS 1: xin=embeds, out fst = sum - embeds[r]; order0 = sum v
// PASS 2: xin=fst (first cnt1), out emb1 = sum - (1+order0)*fst; num1, order1
// PASS 3: xin=emb1 (first cnt12), fused scoring epilogue
template<int PASS>
__global__ void k_pass(const float2* __restrict__ embeds, float* __restrict__ out,
                       unsigned n0, unsigned n1) {
    unsigned t = blockIdx.x * blockDim.x + threadIdx.x;
    int w = (int)(t >> 5);
    int c = (int)(t & 31u);
    if (w >= N_) return;

    const float2* xin = (PASS == 1) ? embeds : (PASS == 2 ? g_fst : g_emb1);
    const float* numin = (PASS == 2) ? g_order0 : g_num1;

    int beg = __ldg(&g_rowptr[w]);
    unsigned seg = __ldg(&g_seg[w]);
    int cnt = (PASS == 1) ? (__ldg(&g_rowptr[w + 1]) - beg)
            : (PASS == 2) ? (int)(seg >> 16)
                          : (int)(seg & 0xFFFFu);

    float ax = 0.f, ay = 0.f;
    float ns = 0.f, o1acc = 0.f;

    #pragma unroll 8
    for (int e = beg; e < beg + cnt; ++e) {
        uint2 er = __ldg(&g_edge[e]);
        float v = __uint_as_float(er.y);
        float2 x = __ldg(&xin[(size_t)er.x * 32 + c]);
        ax += v * x.x; ay += v * x.y;
        if (PASS == 1) ns += v;
        else           ns += v * __ldg(&numin[er.x]);
        if (PASS == 2) o1acc += v;
    }

    size_t idx = (size_t)w * 32 + c;

    if (PASS == 1) {
        float2 b = __ldg(&embeds[idx]);
        g_fst[idx] = make_float2(ax - b.x, ay - b.y);
        if (c == 0) g_order0[w] = ns;
    } else if (PASS == 2) {
        float o = __ldg(&g_order0[w]);
        float f = 1.0f + o;
        float2 p = __ldg(&g_fst[idx]);
        g_emb1[idx] = make_float2(ax - f * p.x, ay - f * p.y);
        if (c == 0) { g_num1[w] = ns - 2.0f * o; g_order1[w] = o1acc; }
    } else {
        float o1  = __ldg(&g_order1[w]);
        float o0  = __ldg(&g_order0[w]);
        float n1v = __ldg(&g_num1[w]);
        float f = 1.0f + o1;
        float2 e1 = __ldg(&g_emb1[idx]);
        float2 p  = __ldg(&g_fst[idx]);
        float2 b  = __ldg(&embeds[idx]);
        float e2x = ax - f * e1.x, e2y = ay - f * e1.y;
        float num2 = ns - n1v - o1;
        float inv = 1.0f / (o0 + n1v + num2 + 1e-8f);
        float sx = (p.x + e1.x + e2x) * inv;
        float sy = (p.y + e1.y + e2y) * inv;
        float sa = sx * sx + sy * sy;
        float sb = b.x * b.x + b.y * b.y;
        float dp = sx * b.x + sy * b.y;
        for (int off = 16; off > 0; off >>= 1) {
            sa += __shfl_down_sync(0xFFFFFFFFu, sa, off);
            sb += __shfl_down_sync(0xFFFFFFFFu, sb, off);
            dp += __shfl_down_sync(0xFFFFFFFFu, dp, off);
        }
        if (c == 0) {
            float na = sqrtf(sa); if (na < 1e-12f) na = 1e-12f;
            float nb = sqrtf(sb); if (nb < 1e-12f) nb = 1e-12f;
            float score = dp / (na * nb);
            unsigned bits = rb32(n0, n1, (unsigned)w);
            float u = __uint_as_float(0x3F800000u | (bits >> 9)) - 1.0f;
            score += -logf(-logf(u));
            out[w] = score;
            unsigned kk = __float_as_uint(score);
            kk = (kk & 0x80000000u) ? ~kk : (kk | 0x80000000u);
            g_keys[w] = kk;
        }
    }
}

// ---- fused radix histogram + scan (last-block ticket) ----
__global__ void k_histscan(int pass) {
    __shared__ unsigned sh[256];
    __shared__ int s_last;
    int tid = threadIdx.x;
    if (tid < 256) sh[tid] = 0u;
    __syncthreads();

    int i = blockIdx.x * blockDim.x + tid;
    int shift = 24 - 8 * pass;
    unsigned pmask = (pass == 0) ? 0u : (0xFFFFFFFFu << (shift + 8));
    unsigned pref = g_prefix;
    if (i < N_) {
        unsigned k = g_keys[i];
        if ((k & pmask) == pref)
            atomicAdd(&sh[(k >> shift) & 255u], 1u);
    }
    __syncthreads();
    if (tid < 256 && sh[tid]) atomicAdd(&g_hist[tid], sh[tid]);
    __threadfence();
    __syncthreads();
    if (tid == 0)
        s_last = (atomicAdd(&g_ticket, 1) == (int)gridDim.x - 1) ? 1 : 0;
    __syncthreads();
    if (!s_last) return;

    if (tid == 0) {
        int K = g_rem;
        unsigned c = 0;
        int d;
        for (d = 255; d >= 0; d--) {
            unsigned h = *((volatile unsigned*)&g_hist[d]);
            if (c + h >= (unsigned)K) break;
            c += h;
        }
        if (d < 0) d = 0;
        g_prefix = pref | (((unsigned)d) << shift);
        g_rem = K - (int)c;
        g_ticket = 0;
    }
    __syncthreads();
    if (tid < 256) g_hist[tid] = 0u;
}

// collect everything >= 24-bit prefix threshold (>=1024, <CAP candidates)
__global__ void k_select() {
    int i = blockIdx.x * blockDim.x + threadIdx.x;
    if (i >= N_) return;
    unsigned k = g_keys[i];
    if (k >= g_prefix) {
        int p = atomicAdd(&g_selcount, 1);
        if (p < CAP)
            g_cand[p] = (((unsigned long long)k) << 32) | (unsigned)(~(unsigned)i);
    }
}

__global__ void k_sort(float* __restrict__ out) {
    __shared__ unsigned long long sm[CAP];
    int tid = threadIdx.x;
    int cnt = g_selcount; if (cnt > CAP) cnt = CAP;
    for (int s = 0; s < CAP / 1024; s++) {
        int i = tid + s * 1024;
        sm[i] = (i < cnt) ? g_cand[i] : 0ull;
    }
    __syncthreads();
    for (int k = 2; k <= CAP; k <<= 1) {
        for (int j = k >> 1; j > 0; j >>= 1) {
            for (int s = 0; s < CAP / 1024; s++) {
                int i = tid + s * 1024;
                int l = i ^ j;
                if (l > i) {
                    unsigned long long a = sm[i], b = sm[l];
                    bool up = ((i & k) == 0);
                    if ((a < b) == up) { sm[i] = b; sm[l] = a; }
                }
            }
            __syncthreads();
        }
    }
    unsigned idx = ~((unsigned)sm[tid]);
    out[N_ + tid] = (float)idx;
}

// ---------------- launch --------------------------------------------------------
extern "C" void kernel_launch(void* const* d_in, const int* in_sizes, int n_in,
                              void* d_out, int out_size) {
    const int*   rows   = (const int*)d_in[0];
    const int*   cols   = (const int*)d_in[1];
    const float* vals   = (const float*)d_in[2];
    const float* embeds = (const float*)d_in[3];
    float* out = (float*)d_out;

    // key chain (partitionable): key(42) -> (split) kd1 -> (split) kd2 -> (split) kn
    unsigned k0 = 0u, k1 = 42u, nk[2], kd1[2], kd2[2], kn[2];
    jax_split_part(k0, k1, nk, kd1); k0 = nk[0]; k1 = nk[1];
    jax_split_part(k0, k1, nk, kd2); k0 = nk[0]; k1 = nk[1];
    jax_split_part(k0, k1, nk, kn);

    const int B = 256;
    const int gN   = (N_ + B - 1) / B;
    const int gN32 = (N_ * 32 + B - 1) / B;
    const int gE   = (E_ + B - 1) / B;
    const int gH   = (N_ + 511) / 512;

    k_zero<<<gN, B>>>();
    k_count<<<gE, B>>>(rows, kd1[0], kd1[1], kd2[0], kd2[1]);
    k_scanA<<<NBLK, SCAN_B>>>();
    k_scanB<<<1, 512>>>();
    k_scanC<<<NBLK, SCAN_B>>>();
    k_fill<<<gE, B>>>(rows, cols, vals);

    k_pass<1><<<gN32, B>>>((const float2*)embeds, out, kn[0], kn[1]);
    k_pass<2><<<gN32, B>>>((const float2*)embeds, out, kn[0], kn[1]);
    k_pass<3><<<gN32, B>>>((const float2*)embeds, out, kn[0], kn[1]);

    for (int p = 0; p < 3; p++)
        k_histscan<<<gH, 512>>>(p);
    k_select<<<gN, B>>>();
    k_sort<<<1, 1024>>>(out);
}

// round 6
// speedup vs baseline: 1.1169x; 1.1169x over previous
#include <cuda_runtime.h>
#include <cstdint>

#define N_ 100000
#define E_ 3200000
#define NCAND 1024
#define CAP 4096
#define SCAN_B 256
#define NBLK ((N_ + SCAN_B - 1) / SCAN_B)   // 391

// ---------------- device scratch (static, no runtime allocation) ----------------
__device__ float2 g_fst [N_*32];
__device__ float2 g_emb1[N_*32];
__device__ uint2  g_edge[E_];          // CSR records: (col, val bits), segmented
__device__ unsigned char g_cls[E_];    // 0 = m12, 1 = m1-only, 2 = dropped
__device__ float  g_order0[N_];
__device__ float  g_order1[N_];
__device__ float  g_num1[N_];
__device__ unsigned g_cnt[N_];         // packed: deg | cnt_m1<<10 | cnt_m12<<20
__device__ unsigned g_cursor[N_];      // packed per-class cursors
__device__ unsigned g_seg[N_];         // cnt_m12 | cnt_m1<<16
__device__ int    g_rowptr[N_ + 1];
__device__ int    g_blocktot[NBLK];
__device__ int    g_blockoff[NBLK];
__device__ unsigned g_keys[N_];
__device__ unsigned g_hist[256];
__device__ unsigned g_prefix;
__device__ int g_rem;
__device__ int g_ticket;
__device__ int g_selcount;
__device__ unsigned long long g_cand[CAP];

// ---------------- Threefry-2x32 (20 rounds, 5 key injections) -------------------
#define TFR(a,b,r) { a += b; b = ((b << (r)) | (b >> (32-(r)))); b ^= a; }

__host__ __device__ __forceinline__ void tf2x32(unsigned k0, unsigned k1,
                                                unsigned& x0, unsigned& x1) {
    unsigned k2 = k0 ^ k1 ^ 0x1BD11BDAu;
    x0 += k0; x1 += k1;
    TFR(x0,x1,13) TFR(x0,x1,15) TFR(x0,x1,26) TFR(x0,x1,6)
    x0 += k1; x1 += k2 + 1u;
    TFR(x0,x1,17) TFR(x0,x1,29) TFR(x0,x1,16) TFR(x0,x1,24)
    x0 += k2; x1 += k0 + 2u;
    TFR(x0,x1,13) TFR(x0,x1,15) TFR(x0,x1,26) TFR(x0,x1,6)
    x0 += k0; x1 += k1 + 3u;
    TFR(x0,x1,17) TFR(x0,x1,29) TFR(x0,x1,16) TFR(x0,x1,24)
    x0 += k1; x1 += k2 + 4u;
    TFR(x0,x1,13) TFR(x0,x1,15) TFR(x0,x1,26) TFR(x0,x1,6)
    x0 += k2; x1 += k0 + 5u;
}

static void jax_split_part(unsigned k0, unsigned k1, unsigned* nk, unsigned* sk) {
    unsigned a0 = 0u, a1 = 0u; tf2x32(k0, k1, a0, a1);
    unsigned b0 = 0u, b1 = 1u; tf2x32(k0, k1, b0, b1);
    nk[0] = a0; nk[1] = a1;
    sk[0] = b0; sk[1] = b1;
}

__device__ __forceinline__ unsigned rb32(unsigned k0, unsigned k1, unsigned i) {
    unsigned x0 = 0u, x1 = i;
    tf2x32(k0, k1, x0, x1);
    return x0 ^ x1;
}

// ---------------- kernels -------------------------------------------------------

__global__ void k_zero() {
    int i = blockIdx.x * blockDim.x + threadIdx.x;
    if (i < N_) { g_cnt[i] = 0u; g_cursor[i] = 0u; }
    if (i < 256) g_hist[i] = 0u;
    if (i == 0) {
        g_prefix = 0u; g_rem = NCAND; g_selcount = 0; g_ticket = 0;
        g_rowptr[N_] = E_;
    }
}

// RNG masks (stored) + packed per-row class counts (single atomic per edge)
__global__ void k_count(const int* __restrict__ rows,
                        unsigned a0, unsigned a1, unsigned b0, unsigned b1) {
    int e = blockIdx.x * blockDim.x + threadIdx.x;
    if (e >= E_) return;
    unsigned u1 = rb32(a0, a1, (unsigned)e);
    unsigned u2 = rb32(b0, b1, (unsigned)e);
    unsigned m1  = (u1 >= 0x80000000u) ? 1u : 0u;           // keep prob 0.5
    unsigned m12 = (m1 && u2 >= 0xC0000000u) ? 1u : 0u;     // joint keep
    g_cls[e] = (unsigned char)(m12 ? 0 : (m1 ? 1 : 2));
    int r = __ldg(rows + e);
    atomicAdd(&g_cnt[r], 1u + (m1 << 10) + (m12 << 20));
}

// ---- prefix scan over degrees -> rowptr; also emit segment counts ----
__global__ void k_scanA() {
    __shared__ int s[SCAN_B];
    int i = blockIdx.x * SCAN_B + threadIdx.x;
    s[threadIdx.x] = (i < N_) ? (int)(g_cnt[i] & 1023u) : 0;
    __syncthreads();
    for (int off = SCAN_B / 2; off > 0; off >>= 1) {
        if (threadIdx.x < off) s[threadIdx.x] += s[threadIdx.x + off];
        __syncthreads();
    }
    if (threadIdx.x == 0) g_blocktot[blockIdx.x] = s[0];
}

__global__ void k_scanB() {
    __shared__ int s[512];
    int t = threadIdx.x;
    int v0 = (t < NBLK) ? g_blocktot[t] : 0;
    s[t] = v0;
    __syncthreads();
    for (int off = 1; off < 512; off <<= 1) {
        int v = s[t];
        if (t >= off) v += s[t - off];
        __syncthreads();
        s[t] = v;
        __syncthreads();
    }
    if (t < NBLK) g_blockoff[t] = s[t] - v0;   // exclusive
}

__global__ void k_scanC() {
    __shared__ int s[SCAN_B];
    int i = blockIdx.x * SCAN_B + threadIdx.x;
    unsigned pc = (i < N_) ? g_cnt[i] : 0u;
    int d = (int)(pc & 1023u);
    s[threadIdx.x] = d;
    __syncthreads();
    for (int off = 1; off < SCAN_B; off <<= 1) {
        int v = s[threadIdx.x];
        if (threadIdx.x >= off) v += s[threadIdx.x - off];
        __syncthreads();
        s[threadIdx.x] = v;
        __syncthreads();
    }
    if (i < N_) {
        g_rowptr[i] = g_blockoff[blockIdx.x] + s[threadIdx.x] - d;
        unsigned cnt1  = (pc >> 10) & 1023u;
        unsigned cnt12 = (pc >> 20) & 1023u;
        g_seg[i] = cnt12 | (cnt1 << 16);
    }
}

// scatter edges into segmented CSR slots: [m12][m1-only][dropped]
__global__ void k_fill(const int* __restrict__ rows, const int* __restrict__ cols,
                       const float* __restrict__ vals) {
    int e = blockIdx.x * blockDim.x + threadIdx.x;
    if (e >= E_) return;
    int cls = (int)g_cls[e];

    int r = __ldg(rows + e);
    unsigned old = atomicAdd(&g_cursor[r], 1u << (10 * cls));
    unsigned within = (old >> (10 * cls)) & ((cls == 2) ? 0xFFFu : 1023u);
    unsigned seg = __ldg(&g_seg[r]);
    unsigned segbase = (cls == 0) ? 0u : ((cls == 1) ? (seg & 0xFFFFu) : (seg >> 16));
    int pos = __ldg(&g_rowptr[r]) + (int)(segbase + within);
    g_edge[pos] = make_uint2((unsigned)__ldg(cols + e), __float_as_uint(__ldg(vals + e)));
}

// ---- gather SpMM passes: 1 warp per row, float2 per lane ----
// PASS 1: xin=embeds, out fst = sum - embeds[r]; order0 = sum v
// PASS 2: xin=fst (first cnt1), out emb1 = sum - (1+order0)*fst; num1, order1
// PASS 3: xin=emb1 (first cnt12), fused scoring epilogue
template<int PASS>
__global__ void k_pass(const float2* __restrict__ embeds, float* __restrict__ out,
                       unsigned n0, unsigned n1) {
    unsigned t = blockIdx.x * blockDim.x + threadIdx.x;
    int w = (int)(t >> 5);
    int c = (int)(t & 31u);
    if (w >= N_) return;

    const float2* xin = (PASS == 1) ? embeds : (PASS == 2 ? g_fst : g_emb1);
    const float* numin = (PASS == 2) ? g_order0 : g_num1;

    int beg = __ldg(&g_rowptr[w]);
    unsigned seg = __ldg(&g_seg[w]);
    int cnt = (PASS == 1) ? (__ldg(&g_rowptr[w + 1]) - beg)
            : (PASS == 2) ? (int)(seg >> 16)
                          : (int)(seg & 0xFFFFu);

    float ax = 0.f, ay = 0.f;
    float ns = 0.f, o1acc = 0.f;

    #pragma unroll 4
    for (int e = beg; e < beg + cnt; ++e) {
        uint2 er = __ldg(&g_edge[e]);
        float v = __uint_as_float(er.y);
        float2 x = __ldg(&xin[(size_t)er.x * 32 + c]);
        ax += v * x.x; ay += v * x.y;
        if (PASS == 1) ns += v;
        else           ns += v * __ldg(&numin[er.x]);
        if (PASS == 2) o1acc += v;
    }

    size_t idx = (size_t)w * 32 + c;

    if (PASS == 1) {
        float2 b = __ldg(&embeds[idx]);
        g_fst[idx] = make_float2(ax - b.x, ay - b.y);
        if (c == 0) g_order0[w] = ns;
    } else if (PASS == 2) {
        float o = __ldg(&g_order0[w]);
        float f = 1.0f + o;
        float2 p = __ldg(&g_fst[idx]);
        g_emb1[idx] = make_float2(ax - f * p.x, ay - f * p.y);
        if (c == 0) { g_num1[w] = ns - 2.0f * o; g_order1[w] = o1acc; }
    } else {
        float o1  = __ldg(&g_order1[w]);
        float o0  = __ldg(&g_order0[w]);
        float n1v = __ldg(&g_num1[w]);
        float f = 1.0f + o1;
        float2 e1 = __ldg(&g_emb1[idx]);
        float2 p  = __ldg(&g_fst[idx]);
        float2 b  = __ldg(&embeds[idx]);
        float e2x = ax - f * e1.x, e2y = ay - f * e1.y;
        float num2 = ns - n1v - o1;
        float inv = 1.0f / (o0 + n1v + num2 + 1e-8f);
        float sx = (p.x + e1.x + e2x) * inv;
        float sy = (p.y + e1.y + e2y) * inv;
        float sa = sx * sx + sy * sy;
        float sb = b.x * b.x + b.y * b.y;
        float dp = sx * b.x + sy * b.y;
        for (int off = 16; off > 0; off >>= 1) {
            sa += __shfl_down_sync(0xFFFFFFFFu, sa, off);
            sb += __shfl_down_sync(0xFFFFFFFFu, sb, off);
            dp += __shfl_down_sync(0xFFFFFFFFu, dp, off);
        }
        if (c == 0) {
            float na = sqrtf(sa); if (na < 1e-12f) na = 1e-12f;
            float nb = sqrtf(sb); if (nb < 1e-12f) nb = 1e-12f;
            float score = dp / (na * nb);
            unsigned bits = rb32(n0, n1, (unsigned)w);
            float u = __uint_as_float(0x3F800000u | (bits >> 9)) - 1.0f;
            score += -logf(-logf(u));
            out[w] = score;
            unsigned kk = __float_as_uint(score);
            kk = (kk & 0x80000000u) ? ~kk : (kk | 0x80000000u);
            g_keys[w] = kk;
        }
    }
}

// ---- fused radix histogram + scan (last-block ticket); 2 rounds, 16-bit prefix ----
__global__ void k_histscan(int pass) {
    __shared__ unsigned sh[256];
    __shared__ int s_last;
    int tid = threadIdx.x;
    if (tid < 256) sh[tid] = 0u;
    __syncthreads();

    int i = blockIdx.x * blockDim.x + tid;
    int shift = 24 - 8 * pass;                 // 24 then 16
    unsigned pmask = (pass == 0) ? 0u : (0xFFFFFFFFu << (shift + 8));
    unsigned pref = g_prefix;
    if (i < N_) {
        unsigned k = g_keys[i];
        if ((k & pmask) == pref)
            atomicAdd(&sh[(k >> shift) & 255u], 1u);
    }
    __syncthreads();
    if (tid < 256 && sh[tid]) atomicAdd(&g_hist[tid], sh[tid]);
    __threadfence();
    __syncthreads();
    if (tid == 0)
        s_last = (atomicAdd(&g_ticket, 1) == (int)gridDim.x - 1) ? 1 : 0;
    __syncthreads();
    if (!s_last) return;

    if (tid == 0) {
        int K = g_rem;
        unsigned c = 0;
        int d;
        for (d = 255; d >= 0; d--) {
            unsigned h = *((volatile unsigned*)&g_hist[d]);
            if (c + h >= (unsigned)K) break;
            c += h;
        }
        if (d < 0) d = 0;
        g_prefix = pref | (((unsigned)d) << shift);
        g_rem = K - (int)c;
        g_ticket = 0;
    }
    __syncthreads();
    if (tid < 256) g_hist[tid] = 0u;
}

// ---- fused select + sort: grid selects candidates; last block bitonic-sorts ----
__global__ void k_selsort(float* __restrict__ out) {
    __shared__ unsigned long long sm[CAP];
    __shared__ int s_last;
    int tid = threadIdx.x;
    unsigned pref = g_prefix;                  // 16-bit threshold prefix (low bits 0)

    int i = blockIdx.x * blockDim.x + tid;
    if (i < N_) {
        unsigned k = g_keys[i];
        if (k >= pref) {
            int p = atomicAdd(&g_selcount, 1);
            if (p < CAP)
                g_cand[p] = (((unsigned long long)k) << 32) | (unsigned)(~(unsigned)i);
        }
    }
    __threadfence();
    __syncthreads();
    if (tid == 0)
        s_last = (atomicAdd(&g_ticket, 1) == (int)gridDim.x - 1) ? 1 : 0;
    __syncthreads();
    if (!s_last) return;

    int cnt = *((volatile int*)&g_selcount); if (cnt > CAP) cnt = CAP;
    for (int s = 0; s < CAP / 1024; s++) {
        int j = tid + s * 1024;
        sm[j] = (j < cnt) ? *((volatile unsigned long long*)&g_cand[j]) : 0ull;
    }
    __syncthreads();
    for (int k = 2; k <= CAP; k <<= 1) {
        for (int j = k >> 1; j > 0; j >>= 1) {
            for (int s = 0; s < CAP / 1024; s++) {
                int a = tid + s * 1024;
                int l = a ^ j;
                if (l > a) {
                    unsigned long long va = sm[a], vb = sm[l];
                    bool up = ((a & k) == 0);
                    if ((va < vb) == up) { sm[a] = vb; sm[l] = va; }
                }
            }
            __syncthreads();
        }
    }
    unsigned idx = ~((unsigned)sm[tid]);
    out[N_ + tid] = (float)idx;
}

// ---------------- launch --------------------------------------------------------
extern "C" void kernel_launch(void* const* d_in, const int* in_sizes, int n_in,
                              void* d_out, int out_size) {
    const int*   rows   = (const int*)d_in[0];
    const int*   cols   = (const int*)d_in[1];
    const float* vals   = (const float*)d_in[2];
    const float* embeds = (const float*)d_in[3];
    float* out = (float*)d_out;

    // key chain (partitionable): key(42) -> (split) kd1 -> (split) kd2 -> (split) kn
    unsigned k0 = 0u, k1 = 42u, nk[2], kd1[2], kd2[2], kn[2];
    jax_split_part(k0, k1, nk, kd1); k0 = nk[0]; k1 = nk[1];
    jax_split_part(k0, k1, nk, kd2); k0 = nk[0]; k1 = nk[1];
    jax_split_part(k0, k1, nk, kn);

    const int B = 256;
    const int gN   = (N_ + B - 1) / B;
    const int gN32 = (N_ * 32 + B - 1) / B;
    const int gE   = (E_ + B - 1) / B;
    const int gH   = (N_ + 511) / 512;
    const int gS   = (N_ + 1023) / 1024;

    k_zero<<<gN, B>>>();
    k_count<<<gE, B>>>(rows, kd1[0], kd1[1], kd2[0], kd2[1]);
    k_scanA<<<NBLK, SCAN_B>>>();
    k_scanB<<<1, 512>>>();
    k_scanC<<<NBLK, SCAN_B>>>();
    k_fill<<<gE, B>>>(rows, cols, vals);

    k_pass<1><<<gN32, B>>>((const float2*)embeds, out, kn[0], kn[1]);
    k_pass<2><<<gN32, B>>>((const float2*)embeds, out, kn[0], kn[1]);
    k_pass<3><<<gN32, B>>>((const float2*)embeds, out, kn[0], kn[1]);

    for (int p = 0; p < 2; p++)
        k_histscan<<<gH, 512>>>(p);
    k_selsort<<<gS, 1024>>>(out);
}

// round 7
// speedup vs baseline: 1.2286x; 1.1000x over previous
#include <cuda_runtime.h>
#include <cstdint>

#define N_ 100000
#define E_ 3200000
#define NCAND 1024
#define CAP 4096
#define SCAN_B 256
#define NBLK ((N_ + SCAN_B - 1) / SCAN_B)   // 391

// ---------------- device scratch (static, no runtime allocation) ----------------
__device__ float2 g_fst [N_*32];
__device__ float2 g_emb1[N_*32];
__device__ uint2  g_edge[E_];          // CSR records: (col, val bits), segmented
__device__ unsigned char g_cls[E_];    // 0 = m12, 1 = m1-only, 2 = dropped
__device__ float  g_order0[N_];
__device__ float  g_order1[N_];
__device__ float  g_num1[N_];
__device__ unsigned g_cnt[N_];         // packed: deg | cnt_m1<<10 | cnt_m12<<20
__device__ unsigned g_cursor[N_];      // packed per-class cursors
__device__ uint2  g_rowseg[N_];        // .x = rowptr, .y = cnt12 | cnt1<<10 | deg<<20
__device__ int    g_blocktot[NBLK];
__device__ int    g_blockoff[NBLK];
__device__ unsigned g_keys[N_];
__device__ unsigned g_hist64[65536];
__device__ unsigned g_prefix;
__device__ int g_ticket;
__device__ int g_ticket2;
__device__ int g_selcount;
__device__ unsigned long long g_cand[CAP];

// ---------------- Threefry-2x32 (20 rounds, 5 key injections) -------------------
#define TFR(a,b,r) { a += b; b = ((b << (r)) | (b >> (32-(r)))); b ^= a; }

__host__ __device__ __forceinline__ void tf2x32(unsigned k0, unsigned k1,
                                                unsigned& x0, unsigned& x1) {
    unsigned k2 = k0 ^ k1 ^ 0x1BD11BDAu;
    x0 += k0; x1 += k1;
    TFR(x0,x1,13) TFR(x0,x1,15) TFR(x0,x1,26) TFR(x0,x1,6)
    x0 += k1; x1 += k2 + 1u;
    TFR(x0,x1,17) TFR(x0,x1,29) TFR(x0,x1,16) TFR(x0,x1,24)
    x0 += k2; x1 += k0 + 2u;
    TFR(x0,x1,13) TFR(x0,x1,15) TFR(x0,x1,26) TFR(x0,x1,6)
    x0 += k0; x1 += k1 + 3u;
    TFR(x0,x1,17) TFR(x0,x1,29) TFR(x0,x1,16) TFR(x0,x1,24)
    x0 += k1; x1 += k2 + 4u;
    TFR(x0,x1,13) TFR(x0,x1,15) TFR(x0,x1,26) TFR(x0,x1,6)
    x0 += k2; x1 += k0 + 5u;
}

static void jax_split_part(unsigned k0, unsigned k1, unsigned* nk, unsigned* sk) {
    unsigned a0 = 0u, a1 = 0u; tf2x32(k0, k1, a0, a1);
    unsigned b0 = 0u, b1 = 1u; tf2x32(k0, k1, b0, b1);
    nk[0] = a0; nk[1] = a1;
    sk[0] = b0; sk[1] = b1;
}

__device__ __forceinline__ unsigned rb32(unsigned k0, unsigned k1, unsigned i) {
    unsigned x0 = 0u, x1 = i;
    tf2x32(k0, k1, x0, x1);
    return x0 ^ x1;
}

// ---------------- kernels -------------------------------------------------------

__global__ void k_zero() {
    int i = blockIdx.x * blockDim.x + threadIdx.x;
    if (i < N_) { g_cnt[i] = 0u; g_cursor[i] = 0u; }
    if (i < 65536) g_hist64[i] = 0u;
    if (i == 0) {
        g_prefix = 0u; g_selcount = 0; g_ticket = 0; g_ticket2 = 0;
    }
}

// RNG masks (stored) + packed per-row class counts (single atomic per edge)
__global__ void k_count(const int* __restrict__ rows,
                        unsigned a0, unsigned a1, unsigned b0, unsigned b1) {
    int e = blockIdx.x * blockDim.x + threadIdx.x;
    if (e >= E_) return;
    unsigned u1 = rb32(a0, a1, (unsigned)e);
    unsigned u2 = rb32(b0, b1, (unsigned)e);
    unsigned m1  = (u1 >= 0x80000000u) ? 1u : 0u;           // keep prob 0.5
    unsigned m12 = (m1 && u2 >= 0xC0000000u) ? 1u : 0u;     // joint keep
    g_cls[e] = (unsigned char)(m12 ? 0 : (m1 ? 1 : 2));
    int r = __ldg(rows + e);
    atomicAdd(&g_cnt[r], 1u + (m1 << 10) + (m12 << 20));
}

// ---- fused block reduce + inter-block scan (last-block ticket) ----
__global__ void k_scanA() {
    __shared__ int s[SCAN_B];
    __shared__ int s_last;
    int tid = threadIdx.x;
    int i = blockIdx.x * SCAN_B + tid;
    s[tid] = (i < N_) ? (int)(g_cnt[i] & 1023u) : 0;
    __syncthreads();
    for (int off = SCAN_B / 2; off > 0; off >>= 1) {
        if (tid < off) s[tid] += s[tid + off];
        __syncthreads();
    }
    if (tid == 0) g_blocktot[blockIdx.x] = s[0];
    __threadfence();
    __syncthreads();
    if (tid == 0)
        s_last = (atomicAdd(&g_ticket2, 1) == NBLK - 1) ? 1 : 0;
    __syncthreads();
    if (!s_last) return;

    // last block: exclusive scan of 391 block totals (padded to 512, 2/thread)
    __shared__ int t2[512];
    int a0 = (tid < NBLK) ? *((volatile int*)&g_blocktot[tid]) : 0;
    int a1 = (tid + 256 < NBLK) ? *((volatile int*)&g_blocktot[tid + 256]) : 0;
    t2[tid] = a0; t2[tid + 256] = a1;
    __syncthreads();
    for (int off = 1; off < 512; off <<= 1) {
        int u0 = t2[tid]       + ((tid >= off)       ? t2[tid - off]       : 0);
        int u1 = t2[tid + 256] + ((tid + 256 >= off) ? t2[tid + 256 - off] : 0);
        __syncthreads();
        t2[tid] = u0; t2[tid + 256] = u1;
        __syncthreads();
    }
    if (tid < NBLK)       g_blockoff[tid]       = t2[tid] - a0;
    if (tid + 256 < NBLK) g_blockoff[tid + 256] = t2[tid + 256] - a1;
}

__global__ void k_scanC() {
    __shared__ int s[SCAN_B];
    int tid = threadIdx.x;
    int i = blockIdx.x * SCAN_B + tid;
    unsigned pc = (i < N_) ? g_cnt[i] : 0u;
    int d = (int)(pc & 1023u);
    s[tid] = d;
    __syncthreads();
    for (int off = 1; off < SCAN_B; off <<= 1) {
        int v = s[tid];
        if (tid >= off) v += s[tid - off];
        __syncthreads();
        s[tid] = v;
        __syncthreads();
    }
    if (i < N_) {
        unsigned rp = (unsigned)(g_blockoff[blockIdx.x] + s[tid] - d);
        unsigned cnt1  = (pc >> 10) & 1023u;
        unsigned cnt12 = (pc >> 20) & 1023u;
        g_rowseg[i] = make_uint2(rp, cnt12 | (cnt1 << 10) | ((unsigned)d << 20));
    }
}

// scatter edges into segmented CSR slots: [m12][m1-only][dropped]
__global__ void k_fill(const int* __restrict__ rows, const int* __restrict__ cols,
                       const float* __restrict__ vals) {
    int e = blockIdx.x * blockDim.x + threadIdx.x;
    if (e >= E_) return;
    int cls = (int)g_cls[e];

    int r = __ldg(rows + e);
    uint2 rs = __ldg(&g_rowseg[r]);
    unsigned old = atomicAdd(&g_cursor[r], 1u << (10 * cls));
    unsigned within = (old >> (10 * cls)) & 1023u;
    unsigned cnt12 = rs.y & 1023u;
    unsigned cnt1  = (rs.y >> 10) & 1023u;
    unsigned segbase = (cls == 0) ? 0u : ((cls == 1) ? cnt12 : cnt1);
    int pos = (int)(rs.x + segbase + within);
    g_edge[pos] = make_uint2((unsigned)__ldg(cols + e), __float_as_uint(__ldg(vals + e)));
}

// ---- gather SpMM passes: 1 warp per row, float2 per lane ----
// PASS 1: xin=embeds, out fst = sum - embeds[r]; order0 = sum v
// PASS 2: xin=fst (first cnt1), out emb1 = sum - (1+order0)*fst; num1, order1
// PASS 3: xin=emb1 (first cnt12), fused scoring + 64K-bin histogram epilogue
template<int PASS>
__global__ void k_pass(const float2* __restrict__ embeds, float* __restrict__ out,
                       unsigned n0, unsigned n1) {
    unsigned t = blockIdx.x * blockDim.x + threadIdx.x;
    int w = (int)(t >> 5);
    int c = (int)(t & 31u);
    if (w >= N_) return;

    const float2* xin = (PASS == 1) ? embeds : (PASS == 2 ? g_fst : g_emb1);
    const float* numin = (PASS == 2) ? g_order0 : g_num1;

    uint2 rs = __ldg(&g_rowseg[w]);
    int beg = (int)rs.x;
    int cnt = (PASS == 1) ? (int)((rs.y >> 20) & 1023u)
            : (PASS == 2) ? (int)((rs.y >> 10) & 1023u)
                          : (int)(rs.y & 1023u);

    float ax = 0.f, ay = 0.f;
    float ns = 0.f, o1acc = 0.f;

    #pragma unroll 4
    for (int e = beg; e < beg + cnt; ++e) {
        uint2 er = __ldg(&g_edge[e]);
        float v = __uint_as_float(er.y);
        float2 x = __ldg(&xin[(size_t)er.x * 32 + c]);
        ax += v * x.x; ay += v * x.y;
        if (PASS == 1) ns += v;
        else           ns += v * __ldg(&numin[er.x]);
        if (PASS == 2) o1acc += v;
    }

    size_t idx = (size_t)w * 32 + c;

    if (PASS == 1) {
        float2 b = __ldg(&embeds[idx]);
        g_fst[idx] = make_float2(ax - b.x, ay - b.y);
        if (c == 0) g_order0[w] = ns;
    } else if (PASS == 2) {
        float o = __ldg(&g_order0[w]);
        float f = 1.0f + o;
        float2 p = __ldg(&g_fst[idx]);
        g_emb1[idx] = make_float2(ax - f * p.x, ay - f * p.y);
        if (c == 0) { g_num1[w] = ns - 2.0f * o; g_order1[w] = o1acc; }
    } else {
        float o1  = __ldg(&g_order1[w]);
        float o0  = __ldg(&g_order0[w]);
        float n1v = __ldg(&g_num1[w]);
        float f = 1.0f + o1;
        float2 e1 = __ldg(&g_emb1[idx]);
        float2 p  = __ldg(&g_fst[idx]);
        float2 b  = __ldg(&embeds[idx]);
        float e2x = ax - f * e1.x, e2y = ay - f * e1.y;
        float num2 = ns - n1v - o1;
        float inv = 1.0f / (o0 + n1v + num2 + 1e-8f);
        float sx = (p.x + e1.x + e2x) * inv;
        float sy = (p.y + e1.y + e2y) * inv;
        float sa = sx * sx + sy * sy;
        float sb = b.x * b.x + b.y * b.y;
        float dp = sx * b.x + sy * b.y;
        for (int off = 16; off > 0; off >>= 1) {
            sa += __shfl_down_sync(0xFFFFFFFFu, sa, off);
            sb += __shfl_down_sync(0xFFFFFFFFu, sb, off);
            dp += __shfl_down_sync(0xFFFFFFFFu, dp, off);
        }
        if (c == 0) {
            float na = sqrtf(sa); if (na < 1e-12f) na = 1e-12f;
            float nb = sqrtf(sb); if (nb < 1e-12f) nb = 1e-12f;
            float score = dp / (na * nb);
            unsigned bits = rb32(n0, n1, (unsigned)w);
            float u = __uint_as_float(0x3F800000u | (bits >> 9)) - 1.0f;
            score += -logf(-logf(u));
            out[w] = score;
            unsigned kk = __float_as_uint(score);
            kk = (kk & 0x80000000u) ? ~kk : (kk | 0x80000000u);
            g_keys[w] = kk;
            atomicAdd(&g_hist64[kk >> 16], 1u);
        }
    }
}

// ---- single-block threshold finder over the 64K-bin histogram ----
__global__ void k_thresh() {
    __shared__ unsigned sup[1024];
    int t = threadIdx.x;
    sup[t] = 0u;
    __syncthreads();
    // transpose-style coalesced accumulation into 1024 superbins (64 bins each)
    for (int j = 0; j < 64; j++) {
        int b = j * 1024 + t;                  // coalesced load
        unsigned h = g_hist64[b];
        if (h) atomicAdd(&sup[b >> 6], h);
    }
    __syncthreads();
    unsigned orig = sup[t];
    // inclusive suffix sum over 1024 superbins
    for (int off = 1; off < 1024; off <<= 1) {
        unsigned v = sup[t] + ((t + off < 1024) ? sup[t + off] : 0u);
        __syncthreads();
        sup[t] = v;
        __syncthreads();
    }
    (void)orig;
    unsigned sufHere = sup[t];
    unsigned sufNext = (t < 1023) ? sup[t + 1] : 0u;
    if (sufHere >= NCAND && sufNext < NCAND) {
        // threshold bin lives in superbin t: walk its 64 bins from the top
        unsigned acc = sufNext;
        int T = t * 64;
        for (int b = 63; b >= 0; --b) {
            acc += g_hist64[t * 64 + b];
            if (acc >= NCAND) { T = t * 64 + b; break; }
        }
        g_prefix = ((unsigned)T) << 16;
    }
}

// ---- fused select + sort: grid selects candidates; last block bitonic-sorts ----
__global__ void k_selsort(float* __restrict__ out) {
    __shared__ unsigned long long sm[CAP];
    __shared__ int s_last;
    int tid = threadIdx.x;
    unsigned pref = g_prefix;                  // 16-bit threshold prefix (low bits 0)

    int i = blockIdx.x * blockDim.x + tid;
    if (i < N_) {
        unsigned k = g_keys[i];
        if (k >= pref) {
            int p = atomicAdd(&g_selcount, 1);
            if (p < CAP)
                g_cand[p] = (((unsigned long long)k) << 32) | (unsigned)(~(unsigned)i);
        }
    }
    __threadfence();
    __syncthreads();
    if (tid == 0)
        s_last = (atomicAdd(&g_ticket, 1) == (int)gridDim.x - 1) ? 1 : 0;
    __syncthreads();
    if (!s_last) return;

    int cnt = *((volatile int*)&g_selcount); if (cnt > CAP) cnt = CAP;
    for (int s = 0; s < CAP / 1024; s++) {
        int j = tid + s * 1024;
        sm[j] = (j < cnt) ? *((volatile unsigned long long*)&g_cand[j]) : 0ull;
    }
    __syncthreads();
    for (int k = 2; k <= CAP; k <<= 1) {
        for (int j = k >> 1; j > 0; j >>= 1) {
            for (int s = 0; s < CAP / 1024; s++) {
                int a = tid + s * 1024;
                int l = a ^ j;
                if (l > a) {
                    unsigned long long va = sm[a], vb = sm[l];
                    bool up = ((a & k) == 0);
                    if ((va < vb) == up) { sm[a] = vb; sm[l] = va; }
                }
            }
            __syncthreads();
        }
    }
    unsigned idx = ~((unsigned)sm[tid]);
    out[N_ + tid] = (float)idx;
}

// ---------------- launch --------------------------------------------------------
extern "C" void kernel_launch(void* const* d_in, const int* in_sizes, int n_in,
                              void* d_out, int out_size) {
    const int*   rows   = (const int*)d_in[0];
    const int*   cols   = (const int*)d_in[1];
    const float* vals   = (const float*)d_in[2];
    const float* embeds = (const float*)d_in[3];
    float* out = (float*)d_out;

    // key chain (partitionable): key(42) -> (split) kd1 -> (split) kd2 -> (split) kn
    unsigned k0 = 0u, k1 = 42u, nk[2], kd1[2], kd2[2], kn[2];
    jax_split_part(k0, k1, nk, kd1); k0 = nk[0]; k1 = nk[1];
    jax_split_part(k0, k1, nk, kd2); k0 = nk[0]; k1 = nk[1];
    jax_split_part(k0, k1, nk, kn);

    const int B = 256;
    const int gN   = (N_ + B - 1) / B;
    const int gN32 = (N_ * 32 + B - 1) / B;
    const int gE   = (E_ + B - 1) / B;
    const int gS   = (N_ + 1023) / 1024;

    k_zero<<<gN, B>>>();
    k_count<<<gE, B>>>(rows, kd1[0], kd1[1], kd2[0], kd2[1]);
    k_scanA<<<NBLK, SCAN_B>>>();
    k_scanC<<<NBLK, SCAN_B>>>();
    k_fill<<<gE, B>>>(rows, cols, vals);

    k_pass<1><<<gN32, B>>>((const float2*)embeds, out, kn[0], kn[1]);
    k_pass<2><<<gN32, B>>>((const float2*)embeds, out, kn[0], kn[1]);
    k_pass<3><<<gN32, B>>>((const float2*)embeds, out, kn[0], kn[1]);

    k_thresh<<<1, 1024>>>();
    k_selsort<<<gS, 1024>>>(out);
}